// round 15
// baseline (speedup 1.0000x reference)
#include <cuda_runtime.h>
#include <math.h>

// ---------------- problem constants ----------------
#define NPIX_TOTAL 33600           // 25600 + 6400 + 1600
#define NDET 3000                  // 3 levels * 1000
#define NOUT 88                    // 85 outputs padded to 88 (1 obj + 80 cls + 4 reg + 3 pad)
#define KDIM 256

// ---------------- device scratch ----------------
__device__ float g_Wall[3][NOUT * KDIM];
__device__ float g_ball[3][NOUT];
__device__ double g_logitsD[(size_t)NOUT * NPIX_TOTAL];   // 23.6 MB probe staging
__device__ unsigned g_key[NPIX_TOTAL];
__device__ int g_labelpx[NPIX_TOTAL];
__device__ float4 g_boxpx[NPIX_TOTAL];
__device__ float g_selScore[NDET];
__device__ int g_selLabel[NDET];
__device__ float4 g_selBox[NDET];
__device__ int g_ord[NDET];
__device__ int g_srtLabel[NDET];
__device__ float4 g_srtBox[NDET];
__device__ int g_srtValid[NDET];
__device__ int g_keep[NDET];

// ---------------- 1) pack weights: rows [obj, cls0..79, reg0..3, pad] ----------------
__global__ void pack_kernel(int level, const float* __restrict__ Wo, const float* __restrict__ bo,
                            const float* __restrict__ Wc, const float* __restrict__ bc,
                            const float* __restrict__ Wr, const float* __restrict__ br) {
    int o = blockIdx.x;      // 0..87
    int c = threadIdx.x;     // 0..255
    float v = 0.0f;
    if (o == 0)            v = Wo[c];
    else if (o <= 80)      v = Wc[(o - 1) * KDIM + c];
    else if (o <= 84)      v = Wr[(o - 81) * KDIM + c];
    g_Wall[level][o * KDIM + c] = v;
    if (c == 0) {
        float b = 0.0f;
        if (o == 0)        b = bo[0];
        else if (o <= 80)  b = bc[o - 1];
        else if (o <= 84)  b = br[o - 81];
        g_ball[level][o] = b;
    }
}

// ---------------- 2) GEMM in FP64 (probe): logits staged to global ----------------
__global__ __launch_bounds__(256) void gemm_kernel(const float* __restrict__ feat, int level,
                                                   int HW, int pixBase) {
    __shared__ __align__(16) struct { float fs[32][128]; float ws[32][NOUT]; } sm;

    const float* Wall = g_Wall[level];
    const int tid = threadIdx.x;
    const int p0 = blockIdx.x * 128;
    const int s = tid & 31;
    const int og = tid >> 5;

    double acc[11][4];
#pragma unroll
    for (int j = 0; j < 11; j++)
#pragma unroll
        for (int q = 0; q < 4; q++) acc[j][q] = 0.0;

    for (int kc = 0; kc < KDIM; kc += 32) {
        for (int i = tid; i < 1024; i += 256) {
            int c = i >> 5;
            int pos = (i & 31) << 2;
            float4 v = make_float4(0.f, 0.f, 0.f, 0.f);
            int p = p0 + pos;
            if (p < HW) v = *(const float4*)(feat + (size_t)(kc + c) * HW + p);
            *(float4*)&sm.fs[c][pos] = v;
        }
        for (int i = tid; i < 32 * NOUT; i += 256) {
            int c = i / NOUT, o = i - c * NOUT;
            sm.ws[c][o] = Wall[o * KDIM + kc + c];
        }
        __syncthreads();
        for (int c = 0; c < 32; c++) {
            float4 f = *(const float4*)&sm.fs[c][s * 4];
            double fx = (double)f.x, fy = (double)f.y, fz = (double)f.z, fw = (double)f.w;
#pragma unroll
            for (int j = 0; j < 11; j++) {
                double w = (double)sm.ws[c][og * 11 + j];
                acc[j][0] = fma(w, fx, acc[j][0]);
                acc[j][1] = fma(w, fy, acc[j][1]);
                acc[j][2] = fma(w, fz, acc[j][2]);
                acc[j][3] = fma(w, fw, acc[j][3]);
            }
        }
        __syncthreads();
    }
#pragma unroll
    for (int j = 0; j < 11; j++) {
        int o = og * 11 + j;
#pragma unroll
        for (int q = 0; q < 4; q++) {
            int p = p0 + s * 4 + q;
            if (p < HW)
                g_logitsD[(size_t)o * NPIX_TOTAL + pixBase + p] = acc[j][q];
        }
    }
}

// ---------------- 2b) epilogue in FP64: scores/labels/boxes from double logits ----------------
__global__ void epilogue_kernel() {
    int gp = blockIdx.x * blockDim.x + threadIdx.x;
    if (gp >= NPIX_TOTAL) return;
    int lvl, base, Wimg; double stride;
    if (gp < 25600)      { lvl = 0; base = 0;     Wimg = 160; stride = 8.0; }
    else if (gp < 32000) { lvl = 1; base = 25600; Wimg = 80;  stride = 16.0; }
    else                 { lvl = 2; base = 32000; Wimg = 40;  stride = 32.0; }
    const float* ball = g_ball[lvl];
    int p = gp - base;

    double obj = g_logitsD[gp] + (double)ball[0];
    double s_obj = 1.0 / (1.0 + exp(-obj));
    double best = -1.0;
    int arg = 0;
    for (int c = 0; c < 80; c++) {
        double lg = g_logitsD[(size_t)(1 + c) * NPIX_TOTAL + gp] + (double)ball[1 + c];
        double pr = s_obj * (1.0 / (1.0 + exp(-lg)));
        if (pr > best) { best = pr; arg = c; }
    }
    double r0 = exp(g_logitsD[(size_t)81 * NPIX_TOTAL + gp] + (double)ball[81]) * stride;
    double r1 = exp(g_logitsD[(size_t)82 * NPIX_TOTAL + gp] + (double)ball[82]) * stride;
    double r2 = exp(g_logitsD[(size_t)83 * NPIX_TOTAL + gp] + (double)ball[83]) * stride;
    double r3 = exp(g_logitsD[(size_t)84 * NPIX_TOTAL + gp] + (double)ball[84]) * stride;
    int y = p / Wimg, x = p - y * Wimg;
    double ax = ((double)x + 0.5) * stride;
    double ay = ((double)y + 0.5) * stride;
    g_key[gp] = __float_as_uint((float)best);    // score > 0 -> bits monotone
    g_labelpx[gp] = arg;
    g_boxpx[gp] = make_float4((float)(ax - r0), (float)(ay - r1),
                              (float)(ax + r2), (float)(ay + r3));
}

// ---------------- bitonic sort (descending) on u64 in smem ----------------
__device__ void bitonic_desc(unsigned long long* sdata, int N, int tid, int nthr) {
    for (int k = 2; k <= N; k <<= 1) {
        for (int j = k >> 1; j > 0; j >>= 1) {
            __syncthreads();
            for (int i = tid; i < N; i += nthr) {
                int l = i ^ j;
                if (l > i) {
                    unsigned long long a = sdata[i], b = sdata[l];
                    bool descBlock = ((i & k) == 0);
                    if (descBlock ? (a < b) : (a > b)) { sdata[i] = b; sdata[l] = a; }
                }
            }
        }
    }
    __syncthreads();
}

// ---------------- 3) exact per-level top-1000 via radix select ----------------
__global__ __launch_bounds__(1024) void topk_kernel() {
    const int HWs[3]   = {25600, 6400, 1600};
    const int bases[3] = {0, 25600, 32000};
    int lvl = blockIdx.x;
    int n = HWs[lvl], base = bases[lvl];
    int tid = threadIdx.x;

    __shared__ unsigned hist8[8][256];
    __shared__ unsigned sh_prefix;
    __shared__ int sh_krem;
    __shared__ int sh_cnt;
    __shared__ unsigned long long cand[2048];

    if (tid == 0) { sh_prefix = 0u; sh_krem = 1000; sh_cnt = 0; }
    __syncthreads();

    for (int pass = 0; pass < 4; pass++) {
        int shift = 24 - 8 * pass;
        for (int i = tid; i < 8 * 256; i += 1024) ((unsigned*)hist8)[i] = 0u;
        __syncthreads();
        unsigned pref = sh_prefix;
        int hb = (tid >> 5) & 7;
        for (int i = tid; i < n; i += 1024) {
            unsigned key = g_key[base + i];
            bool m = (pass == 0) || ((key >> (shift + 8)) == pref);
            if (m) atomicAdd(&hist8[hb][(key >> shift) & 255], 1u);
        }
        __syncthreads();
        if (tid < 256) {
            unsigned t = 0;
            for (int w = 0; w < 8; w++) t += hist8[w][tid];
            hist8[0][tid] = t;
        }
        __syncthreads();
        if (tid == 0) {
            int krem = sh_krem;
            unsigned cum = 0;
            int d = 255;
            for (; d >= 0; d--) {
                cum += hist8[0][d];
                if ((int)cum >= krem) break;
            }
            int above = (int)cum - (int)hist8[0][d];
            sh_krem = krem - above;
            sh_prefix = (pref << 8) | (unsigned)d;
        }
        __syncthreads();
    }
    unsigned T = sh_prefix;  // exact 1000th-largest key
    __syncthreads();

    for (int i = tid; i < n; i += 1024) {
        unsigned key = g_key[base + i];
        if (key >= T) {
            int p = atomicAdd(&sh_cnt, 1);
            if (p < 2048)
                cand[p] = ((unsigned long long)key << 32) | (unsigned)(~(unsigned)(base + i));
        }
    }
    __syncthreads();
    int cnt = sh_cnt < 2048 ? sh_cnt : 2048;
    for (int i = tid; i < 2048; i += 1024)
        if (i >= cnt) cand[i] = 0ULL;
    bitonic_desc(cand, 2048, tid, 1024);

    for (int r = tid; r < 1000; r += 1024) {
        unsigned long long v = cand[r];
        unsigned key = (unsigned)(v >> 32);
        int gpix = (int)(~(unsigned)(v & 0xFFFFFFFFull));
        int o = lvl * 1000 + r;
        g_selScore[o] = __uint_as_float(key);
        g_selLabel[o] = g_labelpx[gpix];
        g_selBox[o]   = g_boxpx[gpix];
    }
}

// ---------------- 4) global sort of 3000 by (score desc, idx asc) ----------------
__global__ __launch_bounds__(1024) void sortall_kernel() {
    __shared__ unsigned long long sdata[4096];
    int tid = threadIdx.x;
    for (int i = tid; i < 4096; i += 1024) {
        if (i < NDET) {
            unsigned key = __float_as_uint(g_selScore[i]);
            sdata[i] = ((unsigned long long)key << 32) | (unsigned)(~(unsigned)i);
        } else sdata[i] = 0ULL;
    }
    bitonic_desc(sdata, 4096, tid, 1024);
    for (int r = tid; r < NDET; r += 1024) {
        unsigned long long v = sdata[r];
        int idx = (int)(~(unsigned)(v & 0xFFFFFFFFull));
        g_ord[r] = idx;
        int lab = g_selLabel[idx];
        g_srtLabel[r] = lab;
        float4 b = g_selBox[idx];
        float off = __fmul_rn((float)lab, 8192.0f);      // CLASS_OFFSET
        g_srtBox[r] = make_float4(__fadd_rn(b.x, off), __fadd_rn(b.y, off),
                                  __fadd_rn(b.z, off), __fadd_rn(b.w, off));
        g_srtValid[r] = (g_selScore[idx] >= 0.05f) ? 1 : 0;
    }
}

// ---------------- 5) zero keep ----------------
__global__ void initkeep_kernel() {
    int i = blockIdx.x * blockDim.x + threadIdx.x;
    if (i < NDET) g_keep[i] = 0;
}

// ---------------- 6) per-class exact serial NMS (class offset => classes independent) ----------------
#define NMS_CAP 1024
__global__ __launch_bounds__(256) void nms_kernel() {
    int cls = blockIdx.x;  // 0..79
    int tid = threadIdx.x;
    __shared__ float sx1[NMS_CAP], sy1[NMS_CAP], sx2[NMS_CAP], sy2[NMS_CAP], sarea[NMS_CAP];
    __shared__ int salive[NMS_CAP];
    __shared__ int srank[NMS_CAP];
    __shared__ int warpCnt[8];
    __shared__ int sBase;

    if (tid == 0) sBase = 0;
    __syncthreads();

    for (int start = 0; start < NDET; start += 256) {
        int r = start + tid;
        bool m = (r < NDET) && (g_srtLabel[r] == cls);
        unsigned bal = __ballot_sync(0xFFFFFFFFu, m);
        int lane = tid & 31, w = tid >> 5;
        if (lane == 0) warpCnt[w] = __popc(bal);
        __syncthreads();
        int wbase = sBase;
        for (int x = 0; x < w; x++) wbase += warpCnt[x];
        int p = wbase + __popc(bal & ((1u << lane) - 1u));
        if (m && p < NMS_CAP) {
            srank[p] = r;
            float4 b = g_srtBox[r];
            sx1[p] = b.x; sy1[p] = b.y; sx2[p] = b.z; sy2[p] = b.w;
            salive[p] = g_srtValid[r];
        }
        __syncthreads();
        if (tid == 0) {
            int t = sBase;
            for (int x = 0; x < 8; x++) t += warpCnt[x];
            sBase = t;
        }
        __syncthreads();
    }
    int n = sBase < NMS_CAP ? sBase : NMS_CAP;

    for (int t = tid; t < n; t += 256)
        sarea[t] = __fmul_rn(__fsub_rn(sx2[t], sx1[t]), __fsub_rn(sy2[t], sy1[t]));
    __syncthreads();

    for (int i = 0; i < n; i++) {
        if (salive[i]) {
            float x1i = sx1[i], y1i = sy1[i], x2i = sx2[i], y2i = sy2[i], ai = sarea[i];
            for (int j = i + 1 + tid; j < n; j += 256) {
                float xx1 = fmaxf(x1i, sx1[j]);
                float yy1 = fmaxf(y1i, sy1[j]);
                float xx2 = fminf(x2i, sx2[j]);
                float yy2 = fminf(y2i, sy2[j]);
                float w = fmaxf(1e-10f, __fsub_rn(xx2, xx1));
                float h = fmaxf(1e-10f, __fsub_rn(yy2, yy1));
                float inter = __fmul_rn(w, h);
                float denom = __fadd_rn(__fsub_rn(__fadd_rn(ai, sarea[j]), inter), 1e-14f);
                float iou = __fdiv_rn(inter, denom);
                if (iou > 0.6f) salive[j] = 0;
            }
        }
        __syncthreads();
    }

    for (int t = tid; t < n; t += 256)
        g_keep[g_ord[srank[t]]] = salive[t];
}

// ---------------- 7) finalize output: [bboxes(12000) | scores(3000) | labels(3000) | keep(3000)] f32 ----------------
__global__ void finalize_kernel(float* __restrict__ out) {
    int i = blockIdx.x * blockDim.x + threadIdx.x;
    if (i < NDET) {
        float4 b = g_selBox[i];
        out[4 * i + 0] = fminf(fmaxf(__fdiv_rn(b.x, 1280.0f), 0.0f), 1.0f);
        out[4 * i + 1] = fminf(fmaxf(__fdiv_rn(b.y, 1280.0f), 0.0f), 1.0f);
        out[4 * i + 2] = fminf(fmaxf(__fdiv_rn(b.z, 1280.0f), 0.0f), 1.0f);
        out[4 * i + 3] = fminf(fmaxf(__fdiv_rn(b.w, 1280.0f), 0.0f), 1.0f);
        out[12000 + i] = g_selScore[i];
        out[15000 + i] = (float)g_selLabel[i];
        out[18000 + i] = g_keep[i] ? 1.0f : 0.0f;
    }
}

// ---------------- launch ----------------
extern "C" void kernel_launch(void* const* d_in, const int* in_sizes, int n_in,
                              void* d_out, int out_size) {
    const int HWs[3]   = {25600, 6400, 1600};
    const int bases[3] = {0, 25600, 32000};

    // Runtime input-order disambiguation (dict order confirmed; keep the guard):
    bool sigOrder = in_sizes[1] > 100000;

    const float* feat[3];
    const float* prm[3][6];
    for (int l = 0; l < 3; l++) {
        if (sigOrder) {
            feat[l] = (const float*)d_in[l];
            for (int j = 0; j < 6; j++) prm[l][j] = (const float*)d_in[3 + 6 * l + j];
        } else {
            feat[l] = (const float*)d_in[7 * l];
            for (int j = 0; j < 6; j++) prm[l][j] = (const float*)d_in[7 * l + 1 + j];
        }
    }

    for (int l = 0; l < 3; l++) {
        pack_kernel<<<NOUT, 256>>>(l, prm[l][0], prm[l][1], prm[l][2], prm[l][3], prm[l][4], prm[l][5]);
    }
    for (int l = 0; l < 3; l++) {
        int grid = (HWs[l] + 127) / 128;
        gemm_kernel<<<grid, 256>>>(feat[l], l, HWs[l], bases[l]);
    }
    epilogue_kernel<<<(NPIX_TOTAL + 255) / 256, 256>>>();
    topk_kernel<<<3, 1024>>>();
    sortall_kernel<<<1, 1024>>>();
    initkeep_kernel<<<3, 1024>>>();
    nms_kernel<<<80, 256>>>();
    finalize_kernel<<<(NDET + 255) / 256, 256>>>((float*)d_out);
}

// round 16
// speedup vs baseline: 6.6238x; 6.6238x over previous
#include <cuda_runtime.h>
#include <math.h>

// ---------------- problem constants ----------------
#define NPIX_TOTAL 33600           // 25600 + 6400 + 1600
#define NDET 3000                  // 3 levels * 1000
#define NOUT 88                    // 85 outputs padded to 88 (1 obj + 80 cls + 4 reg + 3 pad)
#define KDIM 256

// ---------------- device scratch ----------------
__device__ float g_Wall[3][NOUT * KDIM];
__device__ float g_ball[3][NOUT];
__device__ float2 g_logit2[(size_t)NOUT * NPIX_TOTAL];   // (hi, lo) compensated logits, 23.6 MB
__device__ unsigned g_key[NPIX_TOTAL];
__device__ int g_labelpx[NPIX_TOTAL];
__device__ float4 g_boxpx[NPIX_TOTAL];
__device__ float g_selScore[NDET];
__device__ int g_selLabel[NDET];
__device__ float4 g_selBox[NDET];
__device__ int g_ord[NDET];
__device__ int g_srtLabel[NDET];
__device__ float4 g_srtBox[NDET];
__device__ int g_srtValid[NDET];
__device__ int g_keep[NDET];

// ---------------- packed f32x2 ops (Blackwell FFMA2 path) ----------------
#define PK_FMA(d, a, b, c) asm("fma.rn.f32x2 %0, %1, %2, %3;" : "=l"(d) : "l"(a), "l"(b), "l"(c))
#define PK_ADD(d, a, b)    asm("add.rn.f32x2 %0, %1, %2;"     : "=l"(d) : "l"(a), "l"(b))
#define PK_MUL(d, a, b)    asm("mul.rn.f32x2 %0, %1, %2;"     : "=l"(d) : "l"(a), "l"(b))
#define PK_NEG1 0xBF800000BF800000ULL   // (-1.0f, -1.0f)

// ---------------- 1) pack weights: rows [obj, cls0..79, reg0..3, pad] ----------------
__global__ void pack_kernel(int level, const float* __restrict__ Wo, const float* __restrict__ bo,
                            const float* __restrict__ Wc, const float* __restrict__ bc,
                            const float* __restrict__ Wr, const float* __restrict__ br) {
    int o = blockIdx.x;      // 0..87
    int c = threadIdx.x;     // 0..255
    float v = 0.0f;
    if (o == 0)            v = Wo[c];
    else if (o <= 80)      v = Wc[(o - 1) * KDIM + c];
    else if (o <= 84)      v = Wr[(o - 81) * KDIM + c];
    g_Wall[level][o * KDIM + c] = v;
    if (c == 0) {
        float b = 0.0f;
        if (o == 0)        b = bo[0];
        else if (o <= 80)  b = bc[o - 1];
        else if (o <= 84)  b = br[o - 81];
        g_ball[level][o] = b;
    }
}

// ---------------- 2) compensated fp32 GEMM (packed f32x2) ----------------
// Per accumulator per k-step: Fast2Sum compensation + FMA product-error capture.
// Residual error ~1e-12 relative — decisions identical to the validated fp64 pipeline.
__global__ __launch_bounds__(256) void gemm_kernel(const float* __restrict__ feat, int level,
                                                   int HW, int pixBase) {
    __shared__ __align__(16) float fs[32][128];
    __shared__ __align__(8) unsigned long long wpk[32][NOUT];   // (w, w) packed

    const float* Wall = g_Wall[level];
    const int tid = threadIdx.x;
    const int p0 = blockIdx.x * 128;
    const int s = tid & 31;        // pixel quad 0..31
    const int og = tid >> 5;       // output group 0..7 (11 outputs each)

    unsigned long long accS[11][2], accC[11][2];
#pragma unroll
    for (int j = 0; j < 11; j++) {
        accS[j][0] = 0ULL; accS[j][1] = 0ULL;
        accC[j][0] = 0ULL; accC[j][1] = 0ULL;
    }
    const unsigned long long NEG1 = PK_NEG1;

    for (int kc = 0; kc < KDIM; kc += 32) {
        for (int i = tid; i < 1024; i += 256) {
            int c = i >> 5;
            int pos = (i & 31) << 2;
            float4 v = make_float4(0.f, 0.f, 0.f, 0.f);
            int p = p0 + pos;
            if (p < HW) v = *(const float4*)(feat + (size_t)(kc + c) * HW + p);
            *(float4*)&fs[c][pos] = v;
        }
        for (int i = tid; i < 32 * NOUT; i += 256) {
            int c = i / NOUT, o = i - c * NOUT;
            unsigned u = __float_as_uint(Wall[o * KDIM + kc + c]);
            wpk[c][o] = ((unsigned long long)u << 32) | u;
        }
        __syncthreads();
#pragma unroll 2
        for (int c = 0; c < 32; c++) {
            ulonglong2 f = *(const ulonglong2*)&fs[c][s * 4];   // .x = px(0,1), .y = px(2,3)
#pragma unroll
            for (int j = 0; j < 11; j++) {
                unsigned long long w2 = wpk[c][og * 11 + j];
                unsigned long long nw2;
                PK_MUL(nw2, w2, NEG1);
                // pair 0
                {
                    unsigned long long p, epn, t, st, e;
                    PK_MUL(p, w2, f.x);
                    PK_FMA(epn, nw2, f.x, p);            // p - w*f = -e_prod (exact)
                    PK_ADD(t, accS[j][0], p);            // t = s + p
                    PK_FMA(st, t, NEG1, accS[j][0]);     // s - t
                    PK_ADD(e, st, p);                    // (s - t) + p  (Fast2Sum error)
                    PK_ADD(accC[j][0], accC[j][0], e);
                    PK_FMA(accC[j][0], epn, NEG1, accC[j][0]);  // c += e_prod
                    accS[j][0] = t;
                }
                // pair 1
                {
                    unsigned long long p, epn, t, st, e;
                    PK_MUL(p, w2, f.y);
                    PK_FMA(epn, nw2, f.y, p);
                    PK_ADD(t, accS[j][1], p);
                    PK_FMA(st, t, NEG1, accS[j][1]);
                    PK_ADD(e, st, p);
                    PK_ADD(accC[j][1], accC[j][1], e);
                    PK_FMA(accC[j][1], epn, NEG1, accC[j][1]);
                    accS[j][1] = t;
                }
            }
        }
        __syncthreads();
    }

    // write (hi, lo) logits to global
#pragma unroll
    for (int j = 0; j < 11; j++) {
        int o = og * 11 + j;
#pragma unroll
        for (int q = 0; q < 2; q++) {
#pragma unroll
            for (int h = 0; h < 2; h++) {
                int p = p0 + s * 4 + q * 2 + h;
                if (p < HW) {
                    float hi = __uint_as_float((unsigned)(accS[j][q] >> (h * 32)));
                    float lo = __uint_as_float((unsigned)(accC[j][q] >> (h * 32)));
                    g_logit2[(size_t)o * NPIX_TOTAL + pixBase + p] = make_float2(hi, lo);
                }
            }
        }
    }
}

// ---------------- 2b) epilogue: double decisions from compensated logits ----------------
// Identical decision pipeline to the validated fp64 probe: argmax on logits
// (sigmoid is monotone), score = sigmoid(obj)*sigmoid(max) in double, boxes double.
__global__ void epilogue_kernel() {
    int gp = blockIdx.x * blockDim.x + threadIdx.x;
    if (gp >= NPIX_TOTAL) return;
    int lvl, base, Wimg; double stride;
    if (gp < 25600)      { lvl = 0; base = 0;     Wimg = 160; stride = 8.0; }
    else if (gp < 32000) { lvl = 1; base = 25600; Wimg = 80;  stride = 16.0; }
    else                 { lvl = 2; base = 32000; Wimg = 40;  stride = 32.0; }
    const float* ball = g_ball[lvl];
    int p = gp - base;

    float2 vo = g_logit2[gp];
    double objD = ((double)vo.x + (double)vo.y) + (double)ball[0];
    double s_obj = 1.0 / (1.0 + exp(-objD));

    double mx = -1e300;
    int arg = 0;
    for (int c = 0; c < 80; c++) {
        float2 u = g_logit2[(size_t)(1 + c) * NPIX_TOTAL + gp];
        double lg = ((double)u.x + (double)u.y) + (double)ball[1 + c];
        if (lg > mx) { mx = lg; arg = c; }
    }
    double best = s_obj * (1.0 / (1.0 + exp(-mx)));

    float2 u0 = g_logit2[(size_t)81 * NPIX_TOTAL + gp];
    float2 u1 = g_logit2[(size_t)82 * NPIX_TOTAL + gp];
    float2 u2 = g_logit2[(size_t)83 * NPIX_TOTAL + gp];
    float2 u3 = g_logit2[(size_t)84 * NPIX_TOTAL + gp];
    double r0 = exp(((double)u0.x + (double)u0.y) + (double)ball[81]) * stride;
    double r1 = exp(((double)u1.x + (double)u1.y) + (double)ball[82]) * stride;
    double r2 = exp(((double)u2.x + (double)u2.y) + (double)ball[83]) * stride;
    double r3 = exp(((double)u3.x + (double)u3.y) + (double)ball[84]) * stride;

    int y = p / Wimg, x = p - y * Wimg;
    double ax = ((double)x + 0.5) * stride;
    double ay = ((double)y + 0.5) * stride;
    g_key[gp] = __float_as_uint((float)best);    // score > 0 -> bits monotone
    g_labelpx[gp] = arg;
    g_boxpx[gp] = make_float4((float)(ax - r0), (float)(ay - r1),
                              (float)(ax + r2), (float)(ay + r3));
}

// ---------------- bitonic sort (descending) on u64 in smem ----------------
__device__ void bitonic_desc(unsigned long long* sdata, int N, int tid, int nthr) {
    for (int k = 2; k <= N; k <<= 1) {
        for (int j = k >> 1; j > 0; j >>= 1) {
            __syncthreads();
            for (int i = tid; i < N; i += nthr) {
                int l = i ^ j;
                if (l > i) {
                    unsigned long long a = sdata[i], b = sdata[l];
                    bool descBlock = ((i & k) == 0);
                    if (descBlock ? (a < b) : (a > b)) { sdata[i] = b; sdata[l] = a; }
                }
            }
        }
    }
    __syncthreads();
}

// ---------------- 3) exact per-level top-1000 via radix select ----------------
__global__ __launch_bounds__(1024) void topk_kernel() {
    const int HWs[3]   = {25600, 6400, 1600};
    const int bases[3] = {0, 25600, 32000};
    int lvl = blockIdx.x;
    int n = HWs[lvl], base = bases[lvl];
    int tid = threadIdx.x;

    __shared__ unsigned hist8[8][256];
    __shared__ unsigned sh_prefix;
    __shared__ int sh_krem;
    __shared__ int sh_cnt;
    __shared__ unsigned long long cand[2048];

    if (tid == 0) { sh_prefix = 0u; sh_krem = 1000; sh_cnt = 0; }
    __syncthreads();

    for (int pass = 0; pass < 4; pass++) {
        int shift = 24 - 8 * pass;
        for (int i = tid; i < 8 * 256; i += 1024) ((unsigned*)hist8)[i] = 0u;
        __syncthreads();
        unsigned pref = sh_prefix;
        int hb = (tid >> 5) & 7;
        for (int i = tid; i < n; i += 1024) {
            unsigned key = g_key[base + i];
            bool m = (pass == 0) || ((key >> (shift + 8)) == pref);
            if (m) atomicAdd(&hist8[hb][(key >> shift) & 255], 1u);
        }
        __syncthreads();
        if (tid < 256) {
            unsigned t = 0;
            for (int w = 0; w < 8; w++) t += hist8[w][tid];
            hist8[0][tid] = t;
        }
        __syncthreads();
        if (tid == 0) {
            int krem = sh_krem;
            unsigned cum = 0;
            int d = 255;
            for (; d >= 0; d--) {
                cum += hist8[0][d];
                if ((int)cum >= krem) break;
            }
            int above = (int)cum - (int)hist8[0][d];
            sh_krem = krem - above;
            sh_prefix = (pref << 8) | (unsigned)d;
        }
        __syncthreads();
    }
    unsigned T = sh_prefix;  // exact 1000th-largest key
    __syncthreads();

    for (int i = tid; i < n; i += 1024) {
        unsigned key = g_key[base + i];
        if (key >= T) {
            int p = atomicAdd(&sh_cnt, 1);
            if (p < 2048)
                cand[p] = ((unsigned long long)key << 32) | (unsigned)(~(unsigned)(base + i));
        }
    }
    __syncthreads();
    int cnt = sh_cnt < 2048 ? sh_cnt : 2048;
    for (int i = tid; i < 2048; i += 1024)
        if (i >= cnt) cand[i] = 0ULL;
    bitonic_desc(cand, 2048, tid, 1024);

    for (int r = tid; r < 1000; r += 1024) {
        unsigned long long v = cand[r];
        unsigned key = (unsigned)(v >> 32);
        int gpix = (int)(~(unsigned)(v & 0xFFFFFFFFull));
        int o = lvl * 1000 + r;
        g_selScore[o] = __uint_as_float(key);
        g_selLabel[o] = g_labelpx[gpix];
        g_selBox[o]   = g_boxpx[gpix];
    }
}

// ---------------- 4) global sort of 3000 by (score desc, idx asc) ----------------
__global__ __launch_bounds__(1024) void sortall_kernel() {
    __shared__ unsigned long long sdata[4096];
    int tid = threadIdx.x;
    for (int i = tid; i < 4096; i += 1024) {
        if (i < NDET) {
            unsigned key = __float_as_uint(g_selScore[i]);
            sdata[i] = ((unsigned long long)key << 32) | (unsigned)(~(unsigned)i);
        } else sdata[i] = 0ULL;
    }
    bitonic_desc(sdata, 4096, tid, 1024);
    for (int r = tid; r < NDET; r += 1024) {
        unsigned long long v = sdata[r];
        int idx = (int)(~(unsigned)(v & 0xFFFFFFFFull));
        g_ord[r] = idx;
        int lab = g_selLabel[idx];
        g_srtLabel[r] = lab;
        float4 b = g_selBox[idx];
        float off = __fmul_rn((float)lab, 8192.0f);      // CLASS_OFFSET
        g_srtBox[r] = make_float4(__fadd_rn(b.x, off), __fadd_rn(b.y, off),
                                  __fadd_rn(b.z, off), __fadd_rn(b.w, off));
        g_srtValid[r] = (g_selScore[idx] >= 0.05f) ? 1 : 0;
    }
}

// ---------------- 5) zero keep ----------------
__global__ void initkeep_kernel() {
    int i = blockIdx.x * blockDim.x + threadIdx.x;
    if (i < NDET) g_keep[i] = 0;
}

// ---------------- 6) per-class exact serial NMS (class offset => classes independent) ----------------
#define NMS_CAP 1024
__global__ __launch_bounds__(256) void nms_kernel() {
    int cls = blockIdx.x;  // 0..79
    int tid = threadIdx.x;
    __shared__ float sx1[NMS_CAP], sy1[NMS_CAP], sx2[NMS_CAP], sy2[NMS_CAP], sarea[NMS_CAP];
    __shared__ int salive[NMS_CAP];
    __shared__ int srank[NMS_CAP];
    __shared__ int warpCnt[8];
    __shared__ int sBase;

    if (tid == 0) sBase = 0;
    __syncthreads();

    for (int start = 0; start < NDET; start += 256) {
        int r = start + tid;
        bool m = (r < NDET) && (g_srtLabel[r] == cls);
        unsigned bal = __ballot_sync(0xFFFFFFFFu, m);
        int lane = tid & 31, w = tid >> 5;
        if (lane == 0) warpCnt[w] = __popc(bal);
        __syncthreads();
        int wbase = sBase;
        for (int x = 0; x < w; x++) wbase += warpCnt[x];
        int p = wbase + __popc(bal & ((1u << lane) - 1u));
        if (m && p < NMS_CAP) {
            srank[p] = r;
            float4 b = g_srtBox[r];
            sx1[p] = b.x; sy1[p] = b.y; sx2[p] = b.z; sy2[p] = b.w;
            salive[p] = g_srtValid[r];
        }
        __syncthreads();
        if (tid == 0) {
            int t = sBase;
            for (int x = 0; x < 8; x++) t += warpCnt[x];
            sBase = t;
        }
        __syncthreads();
    }
    int n = sBase < NMS_CAP ? sBase : NMS_CAP;

    for (int t = tid; t < n; t += 256)
        sarea[t] = __fmul_rn(__fsub_rn(sx2[t], sx1[t]), __fsub_rn(sy2[t], sy1[t]));
    __syncthreads();

    for (int i = 0; i < n; i++) {
        if (salive[i]) {
            float x1i = sx1[i], y1i = sy1[i], x2i = sx2[i], y2i = sy2[i], ai = sarea[i];
            for (int j = i + 1 + tid; j < n; j += 256) {
                float xx1 = fmaxf(x1i, sx1[j]);
                float yy1 = fmaxf(y1i, sy1[j]);
                float xx2 = fminf(x2i, sx2[j]);
                float yy2 = fminf(y2i, sy2[j]);
                float w = fmaxf(1e-10f, __fsub_rn(xx2, xx1));
                float h = fmaxf(1e-10f, __fsub_rn(yy2, yy1));
                float inter = __fmul_rn(w, h);
                float denom = __fadd_rn(__fsub_rn(__fadd_rn(ai, sarea[j]), inter), 1e-14f);
                float iou = __fdiv_rn(inter, denom);
                if (iou > 0.6f) salive[j] = 0;
            }
        }
        __syncthreads();
    }

    for (int t = tid; t < n; t += 256)
        g_keep[g_ord[srank[t]]] = salive[t];
}

// ---------------- 7) finalize output: [bboxes(12000) | scores(3000) | labels(3000) | keep(3000)] f32 ----------------
__global__ void finalize_kernel(float* __restrict__ out) {
    int i = blockIdx.x * blockDim.x + threadIdx.x;
    if (i < NDET) {
        float4 b = g_selBox[i];
        out[4 * i + 0] = fminf(fmaxf(__fdiv_rn(b.x, 1280.0f), 0.0f), 1.0f);
        out[4 * i + 1] = fminf(fmaxf(__fdiv_rn(b.y, 1280.0f), 0.0f), 1.0f);
        out[4 * i + 2] = fminf(fmaxf(__fdiv_rn(b.z, 1280.0f), 0.0f), 1.0f);
        out[4 * i + 3] = fminf(fmaxf(__fdiv_rn(b.w, 1280.0f), 0.0f), 1.0f);
        out[12000 + i] = g_selScore[i];
        out[15000 + i] = (float)g_selLabel[i];
        out[18000 + i] = g_keep[i] ? 1.0f : 0.0f;
    }
}

// ---------------- launch ----------------
extern "C" void kernel_launch(void* const* d_in, const int* in_sizes, int n_in,
                              void* d_out, int out_size) {
    const int HWs[3]   = {25600, 6400, 1600};
    const int bases[3] = {0, 25600, 32000};

    // Runtime input-order disambiguation (dict order confirmed; keep the guard):
    bool sigOrder = in_sizes[1] > 100000;

    const float* feat[3];
    const float* prm[3][6];
    for (int l = 0; l < 3; l++) {
        if (sigOrder) {
            feat[l] = (const float*)d_in[l];
            for (int j = 0; j < 6; j++) prm[l][j] = (const float*)d_in[3 + 6 * l + j];
        } else {
            feat[l] = (const float*)d_in[7 * l];
            for (int j = 0; j < 6; j++) prm[l][j] = (const float*)d_in[7 * l + 1 + j];
        }
    }

    for (int l = 0; l < 3; l++) {
        pack_kernel<<<NOUT, 256>>>(l, prm[l][0], prm[l][1], prm[l][2], prm[l][3], prm[l][4], prm[l][5]);
    }
    for (int l = 0; l < 3; l++) {
        int grid = (HWs[l] + 127) / 128;
        gemm_kernel<<<grid, 256>>>(feat[l], l, HWs[l], bases[l]);
    }
    epilogue_kernel<<<(NPIX_TOTAL + 255) / 256, 256>>>();
    topk_kernel<<<3, 1024>>>();
    sortall_kernel<<<1, 1024>>>();
    initkeep_kernel<<<3, 1024>>>();
    nms_kernel<<<80, 256>>>();
    finalize_kernel<<<(NDET + 255) / 256, 256>>>((float*)d_out);
}

// round 17
// speedup vs baseline: 11.1122x; 1.6776x over previous
#include <cuda_runtime.h>
#include <math.h>

// ---------------- problem constants ----------------
#define NPIX_TOTAL 33600           // 25600 + 6400 + 1600
#define NDET 3000                  // 3 levels * 1000
#define NOUT 88                    // 85 outputs padded to 88 (1 obj + 80 cls + 4 reg + 3 pad)
#define KDIM 256
#define NTILES 263                 // 200 + 50 + 13 tiles of 128 pixels

// ---------------- device scratch ----------------
__device__ float g_Wall[3][NOUT * KDIM];
__device__ float g_ball[3][NOUT];
__device__ float2 g_logit2[(size_t)NOUT * NPIX_TOTAL];   // (hi, lo) compensated logits
__device__ unsigned g_key[NPIX_TOTAL];
__device__ int g_labelpx[NPIX_TOTAL];
__device__ float4 g_boxpx[NPIX_TOTAL];
__device__ float g_selScore[NDET];
__device__ int g_selLabel[NDET];
__device__ float4 g_selBox[NDET];
__device__ int g_ord[NDET];
__device__ int g_srtLabel[NDET];
__device__ float4 g_srtBox[NDET];
__device__ int g_srtValid[NDET];
__device__ int g_keep[NDET];

// ---------------- packed f32x2 ops (Blackwell FFMA2 path) ----------------
#define PK_FMA(d, a, b, c) asm("fma.rn.f32x2 %0, %1, %2, %3;" : "=l"(d) : "l"(a), "l"(b), "l"(c))
#define PK_ADD(d, a, b)    asm("add.rn.f32x2 %0, %1, %2;"     : "=l"(d) : "l"(a), "l"(b))
#define PK_MUL(d, a, b)    asm("mul.rn.f32x2 %0, %1, %2;"     : "=l"(d) : "l"(a), "l"(b))
#define PK_NEG1 0xBF800000BF800000ULL   // (-1.0f, -1.0f)

// ---------------- 1) pack weights (single launch, all levels) ----------------
struct PackArgs { const float* p[18]; };   // per level: Wo, bo, Wc, bc, Wr, br

__global__ void pack_kernel(PackArgs a) {
    int level = blockIdx.y;
    const float* Wo = a.p[6 * level + 0];
    const float* bo = a.p[6 * level + 1];
    const float* Wc = a.p[6 * level + 2];
    const float* bc = a.p[6 * level + 3];
    const float* Wr = a.p[6 * level + 4];
    const float* br = a.p[6 * level + 5];
    int o = blockIdx.x;      // 0..87
    int c = threadIdx.x;     // 0..255
    float v = 0.0f;
    if (o == 0)            v = Wo[c];
    else if (o <= 80)      v = Wc[(o - 1) * KDIM + c];
    else if (o <= 84)      v = Wr[(o - 81) * KDIM + c];
    g_Wall[level][o * KDIM + c] = v;
    if (c == 0) {
        float b = 0.0f;
        if (o == 0)        b = bo[0];
        else if (o <= 80)  b = bc[o - 1];
        else if (o <= 84)  b = br[o - 81];
        g_ball[level][o] = b;
    }
}

// ---------------- 2) compensated fp32 GEMM, one merged launch ----------------
// 512 threads: pair = tid&63 (2 pixels), og = tid>>6 (11 outputs).
// Per k-step: Fast2Sum sum compensation + FMA product-error capture
// (feature pair negated once per channel, amortized over 11 outputs).
__global__ __launch_bounds__(512, 1) void gemm_kernel(const float* __restrict__ feat0,
                                                      const float* __restrict__ feat1,
                                                      const float* __restrict__ feat2) {
    __shared__ __align__(16) float fs[32][128];
    __shared__ __align__(8) unsigned long long wpk[32][NOUT];   // (w, w) packed

    int t = blockIdx.x;
    const float* feat; int level, p0, HW, pixBase;
    if (t < 200)      { feat = feat0; level = 0; p0 = t * 128;         HW = 25600; pixBase = 0; }
    else if (t < 250) { feat = feat1; level = 1; p0 = (t - 200) * 128; HW = 6400;  pixBase = 25600; }
    else              { feat = feat2; level = 2; p0 = (t - 250) * 128; HW = 1600;  pixBase = 32000; }

    const float* Wall = g_Wall[level];
    const int tid = threadIdx.x;
    const int pair = tid & 63;     // pixels 2*pair, 2*pair+1
    const int og = tid >> 6;       // output group 0..7

    unsigned long long accS[11], accC[11];
#pragma unroll
    for (int j = 0; j < 11; j++) { accS[j] = 0ULL; accC[j] = 0ULL; }
    const unsigned long long NEG1 = PK_NEG1;

    for (int kc = 0; kc < KDIM; kc += 32) {
        for (int i = tid; i < 1024; i += 512) {
            int c = i >> 5;
            int pos = (i & 31) << 2;
            float4 v = make_float4(0.f, 0.f, 0.f, 0.f);
            int p = p0 + pos;
            if (p < HW) v = *(const float4*)(feat + (size_t)(kc + c) * HW + p);
            *(float4*)&fs[c][pos] = v;
        }
        for (int i = tid; i < 32 * NOUT; i += 512) {
            int c = i / NOUT, o = i - c * NOUT;
            unsigned u = __float_as_uint(Wall[o * KDIM + kc + c]);
            wpk[c][o] = ((unsigned long long)u << 32) | u;
        }
        __syncthreads();
#pragma unroll 4
        for (int c = 0; c < 32; c++) {
            unsigned long long f2 = *(const unsigned long long*)&fs[c][pair * 2];
            unsigned long long nf2;
            PK_MUL(nf2, f2, NEG1);
#pragma unroll
            for (int j = 0; j < 11; j++) {
                unsigned long long w2 = wpk[c][og * 11 + j];
                unsigned long long p, epn, tt, st, e;
                PK_MUL(p, w2, f2);
                PK_FMA(epn, w2, nf2, p);            // p - w*f = -e_prod (exact)
                PK_ADD(tt, accS[j], p);             // t = s + p
                PK_FMA(st, tt, NEG1, accS[j]);      // s - t
                PK_ADD(e, st, p);                   // Fast2Sum error
                PK_ADD(accC[j], accC[j], e);
                PK_FMA(accC[j], epn, NEG1, accC[j]); // c += e_prod
                accS[j] = tt;
            }
        }
        __syncthreads();
    }

    // write (hi, lo) logits to global
#pragma unroll
    for (int j = 0; j < 11; j++) {
        int o = og * 11 + j;
#pragma unroll
        for (int h = 0; h < 2; h++) {
            int p = p0 + pair * 2 + h;
            if (p < HW) {
                float hi = __uint_as_float((unsigned)(accS[j] >> (h * 32)));
                float lo = __uint_as_float((unsigned)(accC[j] >> (h * 32)));
                g_logit2[(size_t)o * NPIX_TOTAL + pixBase + p] = make_float2(hi, lo);
            }
        }
    }
}

// ---------------- 2b) epilogue: double decisions from compensated logits ----------------
__global__ void epilogue_kernel() {
    int gp = blockIdx.x * blockDim.x + threadIdx.x;
    if (gp >= NPIX_TOTAL) return;
    int lvl, base, Wimg; double stride;
    if (gp < 25600)      { lvl = 0; base = 0;     Wimg = 160; stride = 8.0; }
    else if (gp < 32000) { lvl = 1; base = 25600; Wimg = 80;  stride = 16.0; }
    else                 { lvl = 2; base = 32000; Wimg = 40;  stride = 32.0; }
    const float* ball = g_ball[lvl];
    int p = gp - base;

    float2 vo = g_logit2[gp];
    double objD = ((double)vo.x + (double)vo.y) + (double)ball[0];
    double s_obj = 1.0 / (1.0 + exp(-objD));

    double mx = -1e300;
    int arg = 0;
    for (int c = 0; c < 80; c++) {
        float2 u = g_logit2[(size_t)(1 + c) * NPIX_TOTAL + gp];
        double lg = ((double)u.x + (double)u.y) + (double)ball[1 + c];
        if (lg > mx) { mx = lg; arg = c; }
    }
    double best = s_obj * (1.0 / (1.0 + exp(-mx)));

    float2 u0 = g_logit2[(size_t)81 * NPIX_TOTAL + gp];
    float2 u1 = g_logit2[(size_t)82 * NPIX_TOTAL + gp];
    float2 u2 = g_logit2[(size_t)83 * NPIX_TOTAL + gp];
    float2 u3 = g_logit2[(size_t)84 * NPIX_TOTAL + gp];
    double r0 = exp(((double)u0.x + (double)u0.y) + (double)ball[81]) * stride;
    double r1 = exp(((double)u1.x + (double)u1.y) + (double)ball[82]) * stride;
    double r2 = exp(((double)u2.x + (double)u2.y) + (double)ball[83]) * stride;
    double r3 = exp(((double)u3.x + (double)u3.y) + (double)ball[84]) * stride;

    int y = p / Wimg, x = p - y * Wimg;
    double ax = ((double)x + 0.5) * stride;
    double ay = ((double)y + 0.5) * stride;
    g_key[gp] = __float_as_uint((float)best);    // score > 0 -> bits monotone
    g_labelpx[gp] = arg;
    g_boxpx[gp] = make_float4((float)(ax - r0), (float)(ay - r1),
                              (float)(ax + r2), (float)(ay + r3));
}

// ---------------- bitonic sort (descending) on u64 in smem ----------------
__device__ void bitonic_desc(unsigned long long* sdata, int N, int tid, int nthr) {
    for (int k = 2; k <= N; k <<= 1) {
        for (int j = k >> 1; j > 0; j >>= 1) {
            __syncthreads();
            for (int i = tid; i < N; i += nthr) {
                int l = i ^ j;
                if (l > i) {
                    unsigned long long a = sdata[i], b = sdata[l];
                    bool descBlock = ((i & k) == 0);
                    if (descBlock ? (a < b) : (a > b)) { sdata[i] = b; sdata[l] = a; }
                }
            }
        }
    }
    __syncthreads();
}

// ---------------- 3) exact per-level top-1000 via radix select ----------------
__global__ __launch_bounds__(1024) void topk_kernel() {
    const int HWs[3]   = {25600, 6400, 1600};
    const int bases[3] = {0, 25600, 32000};
    int lvl = blockIdx.x;
    int n = HWs[lvl], base = bases[lvl];
    int tid = threadIdx.x;

    __shared__ unsigned hist8[8][256];
    __shared__ unsigned sh_prefix;
    __shared__ int sh_krem;
    __shared__ int sh_cnt;
    __shared__ unsigned long long cand[2048];

    if (tid == 0) { sh_prefix = 0u; sh_krem = 1000; sh_cnt = 0; }
    __syncthreads();

    for (int pass = 0; pass < 4; pass++) {
        int shift = 24 - 8 * pass;
        for (int i = tid; i < 8 * 256; i += 1024) ((unsigned*)hist8)[i] = 0u;
        __syncthreads();
        unsigned pref = sh_prefix;
        int hb = (tid >> 5) & 7;
        for (int i = tid; i < n; i += 1024) {
            unsigned key = g_key[base + i];
            bool m = (pass == 0) || ((key >> (shift + 8)) == pref);
            if (m) atomicAdd(&hist8[hb][(key >> shift) & 255], 1u);
        }
        __syncthreads();
        if (tid < 256) {
            unsigned t = 0;
            for (int w = 0; w < 8; w++) t += hist8[w][tid];
            hist8[0][tid] = t;
        }
        __syncthreads();
        if (tid == 0) {
            int krem = sh_krem;
            unsigned cum = 0;
            int d = 255;
            for (; d >= 0; d--) {
                cum += hist8[0][d];
                if ((int)cum >= krem) break;
            }
            int above = (int)cum - (int)hist8[0][d];
            sh_krem = krem - above;
            sh_prefix = (pref << 8) | (unsigned)d;
        }
        __syncthreads();
    }
    unsigned T = sh_prefix;  // exact 1000th-largest key
    __syncthreads();

    for (int i = tid; i < n; i += 1024) {
        unsigned key = g_key[base + i];
        if (key >= T) {
            int p = atomicAdd(&sh_cnt, 1);
            if (p < 2048)
                cand[p] = ((unsigned long long)key << 32) | (unsigned)(~(unsigned)(base + i));
        }
    }
    __syncthreads();
    int cnt = sh_cnt < 2048 ? sh_cnt : 2048;
    for (int i = tid; i < 2048; i += 1024)
        if (i >= cnt) cand[i] = 0ULL;
    bitonic_desc(cand, 2048, tid, 1024);

    for (int r = tid; r < 1000; r += 1024) {
        unsigned long long v = cand[r];
        unsigned key = (unsigned)(v >> 32);
        int gpix = (int)(~(unsigned)(v & 0xFFFFFFFFull));
        int o = lvl * 1000 + r;
        g_selScore[o] = __uint_as_float(key);
        g_selLabel[o] = g_labelpx[gpix];
        g_selBox[o]   = g_boxpx[gpix];
    }
}

// ---------------- 4) global sort of 3000 by (score desc, idx asc); also zeros keep ----------------
__global__ __launch_bounds__(1024) void sortall_kernel() {
    __shared__ unsigned long long sdata[4096];
    int tid = threadIdx.x;
    for (int i = tid; i < NDET; i += 1024) g_keep[i] = 0;   // guard vs NMS_CAP overflow
    for (int i = tid; i < 4096; i += 1024) {
        if (i < NDET) {
            unsigned key = __float_as_uint(g_selScore[i]);
            sdata[i] = ((unsigned long long)key << 32) | (unsigned)(~(unsigned)i);
        } else sdata[i] = 0ULL;
    }
    bitonic_desc(sdata, 4096, tid, 1024);
    for (int r = tid; r < NDET; r += 1024) {
        unsigned long long v = sdata[r];
        int idx = (int)(~(unsigned)(v & 0xFFFFFFFFull));
        g_ord[r] = idx;
        int lab = g_selLabel[idx];
        g_srtLabel[r] = lab;
        float4 b = g_selBox[idx];
        float off = __fmul_rn((float)lab, 8192.0f);      // CLASS_OFFSET
        g_srtBox[r] = make_float4(__fadd_rn(b.x, off), __fadd_rn(b.y, off),
                                  __fadd_rn(b.z, off), __fadd_rn(b.w, off));
        g_srtValid[r] = (g_selScore[idx] >= 0.05f) ? 1 : 0;
    }
}

// ---------------- 5) per-class exact serial NMS (class offset => classes independent) ----------------
#define NMS_CAP 1024
__global__ __launch_bounds__(256) void nms_kernel() {
    int cls = blockIdx.x;  // 0..79
    int tid = threadIdx.x;
    __shared__ float sx1[NMS_CAP], sy1[NMS_CAP], sx2[NMS_CAP], sy2[NMS_CAP], sarea[NMS_CAP];
    __shared__ int salive[NMS_CAP];
    __shared__ int srank[NMS_CAP];
    __shared__ int warpCnt[8];
    __shared__ int sBase;

    if (tid == 0) sBase = 0;
    __syncthreads();

    for (int start = 0; start < NDET; start += 256) {
        int r = start + tid;
        bool m = (r < NDET) && (g_srtLabel[r] == cls);
        unsigned bal = __ballot_sync(0xFFFFFFFFu, m);
        int lane = tid & 31, w = tid >> 5;
        if (lane == 0) warpCnt[w] = __popc(bal);
        __syncthreads();
        int wbase = sBase;
        for (int x = 0; x < w; x++) wbase += warpCnt[x];
        int p = wbase + __popc(bal & ((1u << lane) - 1u));
        if (m && p < NMS_CAP) {
            srank[p] = r;
            float4 b = g_srtBox[r];
            sx1[p] = b.x; sy1[p] = b.y; sx2[p] = b.z; sy2[p] = b.w;
            salive[p] = g_srtValid[r];
        }
        __syncthreads();
        if (tid == 0) {
            int t = sBase;
            for (int x = 0; x < 8; x++) t += warpCnt[x];
            sBase = t;
        }
        __syncthreads();
    }
    int n = sBase < NMS_CAP ? sBase : NMS_CAP;

    for (int t = tid; t < n; t += 256)
        sarea[t] = __fmul_rn(__fsub_rn(sx2[t], sx1[t]), __fsub_rn(sy2[t], sy1[t]));
    __syncthreads();

    for (int i = 0; i < n; i++) {
        if (salive[i]) {
            float x1i = sx1[i], y1i = sy1[i], x2i = sx2[i], y2i = sy2[i], ai = sarea[i];
            for (int j = i + 1 + tid; j < n; j += 256) {
                float xx1 = fmaxf(x1i, sx1[j]);
                float yy1 = fmaxf(y1i, sy1[j]);
                float xx2 = fminf(x2i, sx2[j]);
                float yy2 = fminf(y2i, sy2[j]);
                float w = fmaxf(1e-10f, __fsub_rn(xx2, xx1));
                float h = fmaxf(1e-10f, __fsub_rn(yy2, yy1));
                float inter = __fmul_rn(w, h);
                float denom = __fadd_rn(__fsub_rn(__fadd_rn(ai, sarea[j]), inter), 1e-14f);
                float iou = __fdiv_rn(inter, denom);
                if (iou > 0.6f) salive[j] = 0;
            }
        }
        __syncthreads();
    }

    for (int t = tid; t < n; t += 256)
        g_keep[g_ord[srank[t]]] = salive[t];
}

// ---------------- 6) finalize output: [bboxes(12000) | scores(3000) | labels(3000) | keep(3000)] f32 ----------------
__global__ void finalize_kernel(float* __restrict__ out) {
    int i = blockIdx.x * blockDim.x + threadIdx.x;
    if (i < NDET) {
        float4 b = g_selBox[i];
        out[4 * i + 0] = fminf(fmaxf(__fdiv_rn(b.x, 1280.0f), 0.0f), 1.0f);
        out[4 * i + 1] = fminf(fmaxf(__fdiv_rn(b.y, 1280.0f), 0.0f), 1.0f);
        out[4 * i + 2] = fminf(fmaxf(__fdiv_rn(b.z, 1280.0f), 0.0f), 1.0f);
        out[4 * i + 3] = fminf(fmaxf(__fdiv_rn(b.w, 1280.0f), 0.0f), 1.0f);
        out[12000 + i] = g_selScore[i];
        out[15000 + i] = (float)g_selLabel[i];
        out[18000 + i] = g_keep[i] ? 1.0f : 0.0f;
    }
}

// ---------------- launch ----------------
extern "C" void kernel_launch(void* const* d_in, const int* in_sizes, int n_in,
                              void* d_out, int out_size) {
    // Runtime input-order disambiguation (dict order confirmed; keep the guard):
    bool sigOrder = in_sizes[1] > 100000;

    const float* feat[3];
    PackArgs pa;
    for (int l = 0; l < 3; l++) {
        if (sigOrder) {
            feat[l] = (const float*)d_in[l];
            for (int j = 0; j < 6; j++) pa.p[6 * l + j] = (const float*)d_in[3 + 6 * l + j];
        } else {
            feat[l] = (const float*)d_in[7 * l];
            for (int j = 0; j < 6; j++) pa.p[6 * l + j] = (const float*)d_in[7 * l + 1 + j];
        }
    }

    pack_kernel<<<dim3(NOUT, 3), 256>>>(pa);
    gemm_kernel<<<NTILES, 512>>>(feat[0], feat[1], feat[2]);
    epilogue_kernel<<<(NPIX_TOTAL + 255) / 256, 256>>>();
    topk_kernel<<<3, 1024>>>();
    sortall_kernel<<<1, 1024>>>();
    nms_kernel<<<80, 256>>>();
    finalize_kernel<<<(NDET + 255) / 256, 256>>>((float*)d_out);
}